// round 2
// baseline (speedup 1.0000x reference)
#include <cuda_runtime.h>
#include <cuda_bf16.h>

#define B_   512
#define H_   1024
#define KH   3072          // 3 x 1024 split blocks of h
#define KXE  384           // 3 x 128 encoder x blocks
#define KXD  192           // 3 x 64 decoder ft blocks
#define KTE  (KH + KXE)    // 3456
#define KTD  (KH + KXD)    // 3264
#define NE   4096
#define ND   4224          // 4096 gates + 64 ps + 64 pad
#define LDG  4224

// ----------------------- device scratch (no allocs) ------------------------
__device__ __nv_bfloat16 g_Benc[(size_t)NE * KTE];
__device__ __nv_bfloat16 g_Bdec[(size_t)ND * KTD];
__device__ __nv_bfloat16 g_xenc[(size_t)128 * B_ * KXE];
__device__ __nv_bfloat16 g_ftp[(size_t)32 * B_ * KXD];
__device__ __nv_bfloat16 g_hP[(size_t)B_ * KH];
__device__ float         g_h[(size_t)B_ * H_];
__device__ float         g_G[(size_t)B_ * LDG];
__device__ float         g_Wc[(size_t)3072 * H_];
__device__ float         g_wob[3072];

__device__ __forceinline__ __nv_bfloat16 split_val(float w, bool lo) {
    __nv_bfloat16 hi = __float2bfloat16(w);
    if (!lo) return hi;
    return __float2bfloat16(w - __bfloat162float(hi));
}

// ------------------------------ precompute ---------------------------------
__global__ void k_wc(const float* __restrict__ Wi, const float* __restrict__ Wd) {
    int idx = blockIdx.x * 256 + threadIdx.x;          // exact 3072*1024
    int n = idx >> 10, k = idx & 1023;
    const float* wrow = Wi + n * 128 + 64;
    float s = 0.f;
#pragma unroll 8
    for (int o = 0; o < 64; o++) s += wrow[o] * Wd[o * 1024 + k];
    g_Wc[idx] = s;
}

__global__ void k_wob(const float* __restrict__ Wi, const float* __restrict__ bd) {
    int n = blockIdx.x * 256 + threadIdx.x;
    if (n >= 3072) return;
    float s = 0.f;
#pragma unroll 8
    for (int o = 0; o < 64; o++) s += Wi[n * 128 + 64 + o] * bd[o];
    g_wob[n] = s;
}

// Encoder weights (4096 x 3456): [0,2048)=r,z (Wh|Wi); [2048,3072)=n_h (Wh);
// [3072,4096)=n_i (Wi in K range [3072,3456)).
__global__ void build_benc(const float* __restrict__ Wi, const float* __restrict__ Wh) {
    size_t idx = (size_t)blockIdx.x * 256 + threadIdx.x;   // exact NE*KTE
    int p = (int)(idx / KTE);
    int k = (int)(idx - (size_t)p * KTE);
    float w = 0.f; bool lo = false;
    if (p < 2048) {
        if (k < KH) { w = Wh[(size_t)p * 1024 + (k & 1023)]; lo = ((k >> 10) == 2); }
        else        { int j = k - KH; w = Wi[p * 128 + (j & 127)]; lo = ((j >> 7) == 2); }
    } else if (p < 3072) {
        if (k < KH) { w = Wh[(size_t)p * 1024 + (k & 1023)]; lo = ((k >> 10) == 2); }
    } else {
        int q = p - 1024;
        if (k >= KH) { int j = k - KH; w = Wi[q * 128 + (j & 127)]; lo = ((j >> 7) == 2); }
    }
    g_Benc[idx] = split_val(w, lo);
}

// Decoder weights (4224 x 3264): [0,2048)=r,z (Wh+Wc | Wi_f); [2048,3072)=n_h;
// [3072,4096)=n_i (Wc | Wi_f); [4096,4160)=Wd (ps readout); rest pad.
__global__ void build_bdec(const float* __restrict__ Wi, const float* __restrict__ Wh,
                           const float* __restrict__ Wd) {
    size_t idx = (size_t)blockIdx.x * 256 + threadIdx.x;   // exact ND*KTD
    int p = (int)(idx / KTD);
    int k = (int)(idx - (size_t)p * KTD);
    float w = 0.f; bool lo = false;
    if (p < 2048) {
        if (k < KH) { int kk = k & 1023;
                      w = Wh[(size_t)p * 1024 + kk] + g_Wc[(size_t)p * 1024 + kk];
                      lo = ((k >> 10) == 2); }
        else        { int j = k - KH; w = Wi[p * 128 + (j & 63)]; lo = ((j >> 6) == 2); }
    } else if (p < 3072) {
        if (k < KH) { w = Wh[(size_t)p * 1024 + (k & 1023)]; lo = ((k >> 10) == 2); }
    } else if (p < 4096) {
        int q = p - 1024;
        if (k < KH) { w = g_Wc[(size_t)q * 1024 + (k & 1023)]; lo = ((k >> 10) == 2); }
        else        { int j = k - KH; w = Wi[q * 128 + (j & 63)]; lo = ((j >> 6) == 2); }
    } else if (p < 4160) {
        int o = p - 4096;
        if (k < KH) { w = Wd[(size_t)o * 1024 + (k & 1023)]; lo = ((k >> 10) == 2); }
    }
    g_Bdec[idx] = split_val(w, lo);
}

// Encoder activations x_t = [prior_t | labels_t], split into 3 blocks of 128.
__global__ void k_xenc(const float* __restrict__ feats, const float* __restrict__ labels) {
    size_t idx = (size_t)blockIdx.x * 256 + threadIdx.x;   // exact 128*B_*KXE
    int t = (int)(idx / ((size_t)B_ * KXE));
    int rem = (int)(idx - (size_t)t * B_ * KXE);
    int m = rem / KXE;
    int k = rem - m * KXE;
    int blk = k >> 7, kk = k & 127;
    float v = (kk < 64) ? feats[((size_t)m * 159 + t) * 64 + kk]
                        : labels[((size_t)m * 128 + t) * 64 + (kk - 64)];
    g_xenc[idx] = split_val(v, blk == 1);
}

// Decoder ft blocks (3 x 64); slot 31 zero (gates of last iter unused).
__global__ void k_ftp(const float* __restrict__ feats) {
    size_t idx = (size_t)blockIdx.x * 256 + threadIdx.x;   // exact 32*B_*KXD
    int j = (int)(idx / ((size_t)B_ * KXD));
    int rem = (int)(idx - (size_t)j * B_ * KXD);
    int m = rem / KXD;
    int k = rem - m * KXD;
    int blk = k >> 6, kk = k & 63;
    float v = (j == 31) ? 0.f : feats[((size_t)m * 159 + 128 + j) * 64 + kk];
    g_ftp[idx] = split_val(v, blk == 1);
}

__global__ void init_h() {
    int idx = blockIdx.x * 256 + threadIdx.x;              // exact B_*KH
    g_hP[idx] = __float2bfloat16(0.f);
    if (idx < B_ * H_) g_h[idx] = 0.f;
}

// ------------------------------- GEMM --------------------------------------
__device__ __forceinline__ void ldsm4(unsigned& r0, unsigned& r1, unsigned& r2,
                                      unsigned& r3, const void* p) {
    unsigned a = (unsigned)__cvta_generic_to_shared(p);
    asm volatile("ldmatrix.sync.aligned.m8n8.x4.shared.b16 {%0,%1,%2,%3},[%4];"
                 : "=r"(r0), "=r"(r1), "=r"(r2), "=r"(r3) : "r"(a));
}

__device__ __forceinline__ void mma16816(float* c, const unsigned* a,
                                         unsigned b0, unsigned b1) {
    asm volatile(
        "mma.sync.aligned.m16n8k16.row.col.f32.bf16.bf16.f32 "
        "{%0,%1,%2,%3},{%4,%5,%6,%7},{%8,%9},{%0,%1,%2,%3};"
        : "+f"(c[0]), "+f"(c[1]), "+f"(c[2]), "+f"(c[3])
        : "r"(a[0]), "r"(a[1]), "r"(a[2]), "r"(a[3]), "r"(b0), "r"(b1));
}

// G[m0:m0+128, n0:n0+128] = A @ Bmat^T over the region's K range.
// A = [g_hP (K<3072) | x-part (K>=3072)].
__global__ __launch_bounds__(256)
void gemm_step(int mode, int step) {
    __shared__ __nv_bfloat16 As[128][56];
    __shared__ __nv_bfloat16 Bs[128][56];

    const int ntile = blockIdx.x;
    const int n0 = ntile * 128;
    const int m0 = blockIdx.y * 128;
    const int region = ntile >> 3;

    int kbeg, kend, Ktot, K2;
    const __nv_bfloat16 *Bmat, *A2;
    if (mode == 0) {
        kbeg = (region == 3) ? KH : 0;
        kend = (region == 2) ? KH : KTE;
        Ktot = KTE; K2 = KXE;
        Bmat = g_Benc; A2 = g_xenc + (size_t)step * B_ * KXE;
    } else {
        kbeg = 0;
        kend = (region == 2 || region >= 4) ? KH : KTD;
        Ktot = KTD; K2 = KXD;
        Bmat = g_Bdec; A2 = g_ftp + (size_t)step * B_ * KXD;
    }

    const int tid = threadIdx.x;
    const int lane = tid & 31, wid = tid >> 5;
    const int wm = (wid & 3) * 32, wn = (wid >> 2) * 64;
    const int grp = lane >> 2, tig = lane & 3;
    const int lr = tid >> 2;          // 0..63
    const int cg = (tid & 3) * 8;     // 0,8,16,24

    float acc[2][8][4];
#pragma unroll
    for (int i = 0; i < 2; i++)
#pragma unroll
        for (int j = 0; j < 8; j++)
#pragma unroll
            for (int q = 0; q < 4; q++) acc[i][j][q] = 0.f;

    uint4 ra[2], rb[2];
    // prologue fetch
    {
        int kb = kbeg;
#pragma unroll
        for (int i = 0; i < 2; i++) {
            int r = lr + i * 64;
            const __nv_bfloat16* asrc; int lda, kl;
            if (kb < KH) { asrc = g_hP; lda = KH; kl = kb; }
            else         { asrc = A2;   lda = K2; kl = kb - KH; }
            ra[i] = *(const uint4*)(asrc + (size_t)(m0 + r) * lda + kl + cg);
            rb[i] = *(const uint4*)(Bmat + (size_t)(n0 + r) * Ktot + kb + cg);
        }
    }

    for (int kb = kbeg; kb < kend; kb += 32) {
        __syncthreads();
#pragma unroll
        for (int i = 0; i < 2; i++) {
            *(uint4*)&As[lr + i * 64][cg] = ra[i];
            *(uint4*)&Bs[lr + i * 64][cg] = rb[i];
        }
        __syncthreads();

        int kn = kb + 32;
        if (kn < kend) {
#pragma unroll
            for (int i = 0; i < 2; i++) {
                int r = lr + i * 64;
                const __nv_bfloat16* asrc; int lda, kl;
                if (kn < KH) { asrc = g_hP; lda = KH; kl = kn; }
                else         { asrc = A2;   lda = K2; kl = kn - KH; }
                ra[i] = *(const uint4*)(asrc + (size_t)(m0 + r) * lda + kl + cg);
                rb[i] = *(const uint4*)(Bmat + (size_t)(n0 + r) * Ktot + kn + cg);
            }
        }

#pragma unroll
        for (int kh = 0; kh < 32; kh += 16) {
            unsigned a[2][4], b[4][4];
#pragma unroll
            for (int mi = 0; mi < 2; mi++)
                ldsm4(a[mi][0], a[mi][1], a[mi][2], a[mi][3],
                      &As[wm + mi * 16 + (lane & 15)][kh + (lane >> 4) * 8]);
#pragma unroll
            for (int np = 0; np < 4; np++)
                ldsm4(b[np][0], b[np][1], b[np][2], b[np][3],
                      &Bs[wn + np * 16 + (lane & 15)][kh + (lane >> 4) * 8]);
#pragma unroll
            for (int mi = 0; mi < 2; mi++)
#pragma unroll
                for (int nj = 0; nj < 8; nj++) {
                    int np = nj >> 1;
                    unsigned b0 = (nj & 1) ? b[np][1] : b[np][0];
                    unsigned b1 = (nj & 1) ? b[np][3] : b[np][2];
                    mma16816(acc[mi][nj], a[mi], b0, b1);
                }
        }
    }

#pragma unroll
    for (int mi = 0; mi < 2; mi++)
#pragma unroll
        for (int nj = 0; nj < 8; nj++) {
            int row = m0 + wm + mi * 16 + grp;
            int col = n0 + wn + nj * 8 + tig * 2;
            *(float2*)&g_G[(size_t)row * LDG + col] =
                make_float2(acc[mi][nj][0], acc[mi][nj][1]);
            *(float2*)&g_G[(size_t)(row + 8) * LDG + col] =
                make_float2(acc[mi][nj][2], acc[mi][nj][3]);
        }
}

// ------------------------------ pointwise ----------------------------------
__global__ void pointwise(int mode, const float* __restrict__ bi,
                          const float* __restrict__ bh) {
    int idx = blockIdx.x * 256 + threadIdx.x;     // exact 512*1024
    int m = idx >> 10, n = idx & 1023;
    const float* Gr = g_G + (size_t)m * LDG;
    float wr = mode ? g_wob[n] : 0.f;
    float wz = mode ? g_wob[1024 + n] : 0.f;
    float wn_ = mode ? g_wob[2048 + n] : 0.f;
    float r = Gr[n] + bi[n] + bh[n] + wr;
    float z = Gr[1024 + n] + bi[1024 + n] + bh[1024 + n] + wz;
    float ghn = Gr[2048 + n] + bh[2048 + n];
    float gin = Gr[3072 + n] + bi[2048 + n] + wn_;
    r = 1.f / (1.f + __expf(-r));
    z = 1.f / (1.f + __expf(-z));
    float nn = tanhf(gin + r * ghn);
    float ho = g_h[idx];
    float h = (1.f - z) * nn + z * ho;
    g_h[idx] = h;
    __nv_bfloat16 hi = __float2bfloat16(h);
    __nv_bfloat16 lo = __float2bfloat16(h - __bfloat162float(hi));
    g_hP[(size_t)m * KH + n] = hi;
    g_hP[(size_t)m * KH + 1024 + n] = lo;
    g_hP[(size_t)m * KH + 2048 + n] = hi;
}

__global__ void psout(float* __restrict__ out, const float* __restrict__ bd) {
    int idx = blockIdx.x * 256 + threadIdx.x;     // exact 512*64
    int m = idx >> 6, o = idx & 63;
    out[idx] = g_G[(size_t)m * LDG + 4096 + o] + bd[o];
}

// ------------------------------- launch ------------------------------------
extern "C" void kernel_launch(void* const* d_in, const int* in_sizes, int n_in,
                              void* d_out, int out_size) {
    const float* feats  = (const float*)d_in[0];
    const float* labels = (const float*)d_in[1];
    const float* Wi     = (const float*)d_in[2];
    const float* Wh     = (const float*)d_in[3];
    const float* bi     = (const float*)d_in[4];
    const float* bh     = (const float*)d_in[5];
    const float* Wd     = (const float*)d_in[6];
    const float* bd     = (const float*)d_in[7];
    float* out = (float*)d_out;

    k_wc<<<12288, 256>>>(Wi, Wd);
    k_wob<<<12, 256>>>(Wi, bd);
    build_benc<<<(int)(((size_t)NE * KTE) / 256), 256>>>(Wi, Wh);
    build_bdec<<<(int)(((size_t)ND * KTD) / 256), 256>>>(Wi, Wh, Wd);
    k_xenc<<<(int)(((size_t)128 * B_ * KXE) / 256), 256>>>(feats, labels);
    k_ftp<<<(int)(((size_t)32 * B_ * KXD) / 256), 256>>>(feats);
    init_h<<<(B_ * KH) / 256, 256>>>();

    for (int t = 0; t < 128; t++) {
        gemm_step<<<dim3(32, 4), 256>>>(0, t);
        pointwise<<<2048, 256>>>(0, bi, bh);
    }
    for (int j = 0; j < 32; j++) {
        gemm_step<<<dim3(33, 4), 256>>>(1, j);
        psout<<<128, 256>>>(out + (size_t)j * B_ * 64, bd);
        if (j < 31) pointwise<<<2048, 256>>>(1, bi, bh);
    }
}